// round 1
// baseline (speedup 1.0000x reference)
#include <cuda_runtime.h>
#include <math.h>

// Problem geometry: emb (N x 768), prototypes (P x 768), temperature scalar.
// q[n][p] = softmax_p( <emb_n/|emb_n|, c_p/|c_p|> / T ).
// Softmax computed WITHOUT max subtraction (logits bounded in [-10,10], shift-invariant).

#define D_DIM 768
#define BM 128
#define BN 128
#define BK 8
#define MAXN (1 << 17)
#define MAXP (1 << 14)

// Scratch (static device arrays; no allocation allowed)
__device__ float g_inv_na[MAXN];   // 1/||emb_row||
__device__ float g_inv_nb[MAXP];   // 1/||proto_row||
__device__ float g_rowsum[MAXN];   // sum_p exp(logit)

// ---------------------------------------------------------------------------
// Kernel 1: row inverse L2 norms for both matrices; also zeroes g_rowsum.
// One block per row.
// ---------------------------------------------------------------------------
__global__ void norm_kernel(const float* __restrict__ A,
                            const float* __restrict__ B,
                            int N, int P) {
    int row = blockIdx.x;
    const float* src;
    float* dst;
    int r;
    if (row < N) {
        r = row;
        src = A + (size_t)r * D_DIM;
        dst = g_inv_na;
        if (threadIdx.x == 0) g_rowsum[r] = 0.0f;
    } else {
        r = row - N;
        src = B + (size_t)r * D_DIM;
        dst = g_inv_nb;
    }
    float ss = 0.0f;
    for (int i = threadIdx.x; i < D_DIM; i += blockDim.x) {
        float v = src[i];
        ss += v * v;
    }
#pragma unroll
    for (int o = 16; o; o >>= 1) ss += __shfl_xor_sync(0xffffffffu, ss, o);
    __shared__ float sp[8];
    if ((threadIdx.x & 31) == 0) sp[threadIdx.x >> 5] = ss;
    __syncthreads();
    if (threadIdx.x == 0) {
        float t = 0.0f;
        int nw = (blockDim.x + 31) >> 5;
        for (int i = 0; i < nw; i++) t += sp[i];
        float n = fmaxf(sqrtf(t), 1e-12f);
        dst[r] = 1.0f / n;
    }
}

// ---------------------------------------------------------------------------
// Kernel 2: tiled fp32 GEMM (C = A * B^T) with fused scale + exp epilogue.
// Writes exp(logit) to out and accumulates per-row sums into g_rowsum.
// 128x128 tile, 256 threads, 8x8 per-thread microtile, BK=8.
// ---------------------------------------------------------------------------
__global__ void __launch_bounds__(256, 2)
gemm_exp_kernel(const float* __restrict__ A,
                const float* __restrict__ B,
                const float* __restrict__ tptr,
                float* __restrict__ out,
                int N, int P) {
    __shared__ float As[BK][BM];
    __shared__ float Bs[BK][BN];

    const int tid = threadIdx.x;
    const int tx = tid & 15;     // 0..15 -> 8 cols each
    const int ty = tid >> 4;     // 0..15 -> 8 rows each
    const int n0 = blockIdx.y * BM;
    const int p0 = blockIdx.x * BN;

    float acc[8][8];
#pragma unroll
    for (int i = 0; i < 8; i++)
#pragma unroll
        for (int j = 0; j < 8; j++) acc[i][j] = 0.0f;

    // cooperative tile loads: 256 threads, each loads one float4 of A and B
    const int lrow = tid >> 1;          // 0..127
    const int lk = (tid & 1) * 4;       // 0 or 4
    const bool aval = (n0 + lrow) < N;
    const bool bval = (p0 + lrow) < P;
    const float* Ag = A + (size_t)(n0 + lrow) * D_DIM + lk;
    const float* Bg = B + (size_t)(p0 + lrow) * D_DIM + lk;

    for (int k0 = 0; k0 < D_DIM; k0 += BK) {
        float4 a4 = make_float4(0.f, 0.f, 0.f, 0.f);
        float4 b4 = make_float4(0.f, 0.f, 0.f, 0.f);
        if (aval) a4 = *reinterpret_cast<const float4*>(Ag + k0);
        if (bval) b4 = *reinterpret_cast<const float4*>(Bg + k0);
        As[lk + 0][lrow] = a4.x;
        As[lk + 1][lrow] = a4.y;
        As[lk + 2][lrow] = a4.z;
        As[lk + 3][lrow] = a4.w;
        Bs[lk + 0][lrow] = b4.x;
        Bs[lk + 1][lrow] = b4.y;
        Bs[lk + 2][lrow] = b4.z;
        Bs[lk + 3][lrow] = b4.w;
        __syncthreads();
#pragma unroll
        for (int k = 0; k < BK; k++) {
            float a[8], b[8];
#pragma unroll
            for (int i = 0; i < 8; i++) a[i] = As[k][ty * 8 + i];
#pragma unroll
            for (int j = 0; j < 8; j++) b[j] = Bs[k][tx * 8 + j];
#pragma unroll
            for (int i = 0; i < 8; i++)
#pragma unroll
                for (int j = 0; j < 8; j++) acc[i][j] = fmaf(a[i], b[j], acc[i][j]);
        }
        __syncthreads();
    }

    // Epilogue: logit = acc * inv_na[row] * inv_nb[col] / T ; e = exp(logit)
    const float invT = 1.0f / tptr[0];
    float inb[8];
#pragma unroll
    for (int j = 0; j < 8; j++) {
        int col = p0 + tx * 8 + j;
        inb[j] = (col < P) ? g_inv_nb[col] : 0.0f;
    }

#pragma unroll
    for (int i = 0; i < 8; i++) {
        int row = n0 + ty * 8 + i;
        float rs = 0.0f;
        if (row < N) {
            float s = g_inv_na[row] * invT;
            float e[8];
#pragma unroll
            for (int j = 0; j < 8; j++) {
                e[j] = expf(acc[i][j] * s * inb[j]);
                rs += e[j];
            }
            int colbase = p0 + tx * 8;
            if (colbase + 7 < P) {
                float4* o4 = reinterpret_cast<float4*>(out + (size_t)row * P + colbase);
                o4[0] = make_float4(e[0], e[1], e[2], e[3]);
                o4[1] = make_float4(e[4], e[5], e[6], e[7]);
            } else {
#pragma unroll
                for (int j = 0; j < 8; j++)
                    if (colbase + j < P) out[(size_t)row * P + colbase + j] = e[j];
            }
        }
        // reduce rs across the 16 tx lanes of this ty group (all within one warp half)
#pragma unroll
        for (int o = 8; o; o >>= 1) rs += __shfl_xor_sync(0xffffffffu, rs, o);
        if (tx == 0 && row < N) atomicAdd(&g_rowsum[row], rs);
    }
}

// ---------------------------------------------------------------------------
// Kernel 3: q = e / rowsum  (vectorized float4)
// ---------------------------------------------------------------------------
__global__ void scale_kernel(float* __restrict__ out, int N, int P) {
    size_t idx = (size_t)blockIdx.x * blockDim.x + threadIdx.x;
    size_t total4 = ((size_t)N * (size_t)P) >> 2;
    if (idx < total4) {
        int row = (int)((idx << 2) / (size_t)P);
        float inv = 1.0f / g_rowsum[row];
        float4 v = reinterpret_cast<float4*>(out)[idx];
        v.x *= inv;
        v.y *= inv;
        v.z *= inv;
        v.w *= inv;
        reinterpret_cast<float4*>(out)[idx] = v;
    }
}

// ---------------------------------------------------------------------------
extern "C" void kernel_launch(void* const* d_in, const int* in_sizes, int n_in,
                              void* d_out, int out_size) {
    const float* emb = (const float*)d_in[0];
    const float* proto = (const float*)d_in[1];
    const float* temp = (const float*)d_in[2];
    float* out = (float*)d_out;

    const int N = in_sizes[0] / D_DIM;
    const int P = in_sizes[1] / D_DIM;

    // 1) norms + rowsum zeroing
    norm_kernel<<<N + P, 256>>>(emb, proto, N, P);

    // 2) GEMM + exp + rowsum
    dim3 grid((P + BN - 1) / BN, (N + BM - 1) / BM);
    gemm_exp_kernel<<<grid, 256>>>(emb, proto, temp, out, N, P);

    // 3) scale by 1/rowsum
    size_t total4 = ((size_t)N * (size_t)P) >> 2;
    int blocks = (int)((total4 + 255) / 256);
    scale_kernel<<<blocks, 256>>>(out, N, P);
}

// round 3
// speedup vs baseline: 4.0438x; 4.0438x over previous
#include <cuda_runtime.h>
#include <cuda.h>
#include <cstdint>
#include <math.h>

// q[n][p] = softmax_p( <emb_n/|emb_n|, c_p/|c_p|> / T ), no max-subtraction
// (logits bounded in [-10,10], softmax shift-invariant).
// NOTE: toolchain targets compute_103 (no 'a') -> tcgen05 unavailable.
// Use warp-level mma.sync tf32 (HMMA) + ldmatrix + TMA (all non-suffixed PTX).

#define D_DIM 768
#define TM 128
#define TN 128
#define KC 32                        // K floats per chunk (128B rows, SW128)
#define NCH (D_DIM / KC)             // 24
#define PIPE 4
#define A_ST (TM * KC * 4)           // 16384 B
#define B_ST (TN * KC * 4)           // 16384 B
#define SMEM_A_OFF 1024
#define SMEM_B_OFF (SMEM_A_OFF + PIPE * A_ST)
#define SMEM_TOTAL (SMEM_B_OFF + PIPE * B_ST)   // 132096 B

#define OFF_FULL  0
#define OFF_EMPTY 32

#define MAXN (1 << 17)
#define MAXP (1 << 14)
__device__ float g_inv_na[MAXN];
__device__ float g_inv_nb[MAXP];
__device__ float g_rowsum[MAXN];

// ---------------------------------------------------------------------------
// PTX helpers
// ---------------------------------------------------------------------------
__device__ __forceinline__ uint32_t smem_u32(const void* p) {
    uint32_t a;
    asm("{ .reg .u64 t; cvta.to.shared.u64 t, %1; cvt.u32.u64 %0, t; }" : "=r"(a) : "l"(p));
    return a;
}
__device__ __forceinline__ void mbar_init(uint32_t bar, uint32_t cnt) {
    asm volatile("mbarrier.init.shared.b64 [%0], %1;" :: "r"(bar), "r"(cnt) : "memory");
}
__device__ __forceinline__ void mbar_expect_tx(uint32_t bar, uint32_t bytes) {
    asm volatile("mbarrier.arrive.expect_tx.shared.b64 _, [%0], %1;" :: "r"(bar), "r"(bytes) : "memory");
}
__device__ __forceinline__ void mbar_arrive(uint32_t bar) {
    asm volatile("mbarrier.arrive.shared.b64 _, [%0];" :: "r"(bar) : "memory");
}
__device__ __forceinline__ void mbar_wait(uint32_t bar, uint32_t parity) {
    uint32_t done;
    asm volatile(
        "{ .reg .pred p; mbarrier.try_wait.parity.acquire.cta.shared::cta.b64 p, [%1], %2;"
        " selp.b32 %0, 1, 0, p; }" : "=r"(done) : "r"(bar), "r"(parity) : "memory");
    if (!done) {
        asm volatile(
            "{ .reg .pred P1; WL%=:"
            " mbarrier.try_wait.parity.acquire.cta.shared::cta.b64 P1, [%0], %1, 0x989680;"
            " @P1 bra.uni WD%=; bra.uni WL%=; WD%=: }"
            :: "r"(bar), "r"(parity) : "memory");
    }
}
__device__ __forceinline__ void tma2d(uint32_t dst, const void* map, int x, int y, uint32_t bar) {
    asm volatile(
        "cp.async.bulk.tensor.2d.shared::cta.global.tile.mbarrier::complete_tx::bytes "
        "[%0], [%1, {%2, %3}], [%4];"
        :: "r"(dst), "l"(map), "r"(x), "r"(y), "r"(bar) : "memory");
}
__device__ __forceinline__ uint32_t swz(uint32_t off) {   // SW128
    return off ^ ((off >> 3) & 0x70);
}
__device__ __forceinline__ void ldsm4(uint32_t* r, uint32_t addr) {
    asm volatile("ldmatrix.sync.aligned.m8n8.x4.shared.b16 {%0,%1,%2,%3}, [%4];"
                 : "=r"(r[0]), "=r"(r[1]), "=r"(r[2]), "=r"(r[3]) : "r"(addr));
}
__device__ __forceinline__ void mma_tf32(float* d, const uint32_t* a, uint32_t b0, uint32_t b1) {
    asm volatile(
        "mma.sync.aligned.m16n8k8.row.col.f32.tf32.tf32.f32 "
        "{%0,%1,%2,%3}, {%4,%5,%6,%7}, {%8,%9}, {%0,%1,%2,%3};"
        : "+f"(d[0]), "+f"(d[1]), "+f"(d[2]), "+f"(d[3])
        : "r"(a[0]), "r"(a[1]), "r"(a[2]), "r"(a[3]), "r"(b0), "r"(b1));
}
__device__ __forceinline__ float ex2(float x) {
    float y;
    asm("ex2.approx.ftz.f32 %0, %1;" : "=f"(y) : "f"(x));
    return y;
}

// ---------------------------------------------------------------------------
// Kernel 1: warp-per-row inverse L2 norms, zero g_rowsum
// ---------------------------------------------------------------------------
__global__ void norm_kernel(const float* __restrict__ A, const float* __restrict__ B,
                            int N, int P) {
    int w = (blockIdx.x * blockDim.x + threadIdx.x) >> 5;
    int lane = threadIdx.x & 31;
    if (w >= N + P) return;
    const float4* src;
    float* dst;
    int r;
    if (w < N) {
        r = w;
        src = (const float4*)(A + (size_t)r * D_DIM);
        dst = g_inv_na;
        if (lane == 0) g_rowsum[r] = 0.0f;
    } else {
        r = w - N;
        src = (const float4*)(B + (size_t)r * D_DIM);
        dst = g_inv_nb;
    }
    float ss = 0.0f;
#pragma unroll
    for (int i = 0; i < D_DIM / 4 / 32; i++) {
        float4 v = src[lane + 32 * i];
        ss += v.x * v.x + v.y * v.y + v.z * v.z + v.w * v.w;
    }
#pragma unroll
    for (int o = 16; o; o >>= 1) ss += __shfl_xor_sync(0xffffffffu, ss, o);
    if (lane == 0) dst[r] = 1.0f / fmaxf(sqrtf(ss), 1e-12f);
}

// ---------------------------------------------------------------------------
// Kernel 2: one CTA per 128x128 tile. TMA producer warp + 8 mma.sync consumer
// warps (tf32). Fused exp + rowsum epilogue from register accumulators.
// ---------------------------------------------------------------------------
__global__ void __launch_bounds__(288, 1)
gemm_kernel(const __grid_constant__ CUtensorMap tmap_a,
            const __grid_constant__ CUtensorMap tmap_b,
            const float* __restrict__ tptr,
            float* __restrict__ out,
            int N, int P) {
    extern __shared__ char smem[];
    uint32_t sbase = smem_u32(smem);
    const int tid = threadIdx.x, wid = tid >> 5, lane = tid & 31;
    const int ntp = P / TN;
    const int n0 = (blockIdx.x / ntp) * TM;
    const int p0 = (blockIdx.x % ntp) * TN;

    if (tid == 0) {
        for (int s = 0; s < PIPE; s++) {
            mbar_init(sbase + OFF_FULL + s * 8, 1);
            mbar_init(sbase + OFF_EMPTY + s * 8, 8);   // one arrive per consumer warp
        }
    }
    __syncthreads();
    asm volatile("fence.proxy.async.shared::cta;" ::: "memory");

    if (wid == 8) {
        // ---- TMA producer ----
        if (lane == 0) {
            int st = 0, ph = 1;
            for (int c = 0; c < NCH; c++) {
                mbar_wait(sbase + OFF_EMPTY + st * 8, ph);
                mbar_expect_tx(sbase + OFF_FULL + st * 8, A_ST + B_ST);
                tma2d(sbase + SMEM_A_OFF + st * A_ST, &tmap_a, c * KC, n0,
                      sbase + OFF_FULL + st * 8);
                tma2d(sbase + SMEM_B_OFF + st * B_ST, &tmap_b, c * KC, p0,
                      sbase + OFF_FULL + st * 8);
                if (++st == PIPE) { st = 0; ph ^= 1; }
            }
        }
        return;
    }

    // ---- consumers: warp (wm, wn) owns 32x64 subtile ----
    const int wm = wid >> 1;          // 0..3
    const int wn = wid & 1;           // 0..1
    const int lrow = lane & 15;
    const int lunit = lane >> 4;

    float acc[2][8][4];
#pragma unroll
    for (int mt = 0; mt < 2; mt++)
#pragma unroll
        for (int nt = 0; nt < 8; nt++)
#pragma unroll
            for (int q = 0; q < 4; q++) acc[mt][nt][q] = 0.0f;

    int st = 0, ph = 0;
    for (int c = 0; c < NCH; c++) {
        mbar_wait(sbase + OFF_FULL + st * 8, ph);
        const uint32_t abase = sbase + SMEM_A_OFF + st * A_ST;
        const uint32_t bbase = sbase + SMEM_B_OFF + st * B_ST;
#pragma unroll
        for (int ks = 0; ks < 4; ks++) {
            const uint32_t kunit = 2 * ks + lunit;
            uint32_t a[2][4];
#pragma unroll
            for (int mt = 0; mt < 2; mt++) {
                uint32_t off = (uint32_t)(wm * 32 + mt * 16 + lrow) * 128 + kunit * 16;
                ldsm4(a[mt], abase + swz(off));
            }
            uint32_t b[4][4];
#pragma unroll
            for (int bt = 0; bt < 4; bt++) {
                uint32_t off = (uint32_t)(wn * 64 + bt * 16 + lrow) * 128 + kunit * 16;
                ldsm4(b[bt], bbase + swz(off));
            }
#pragma unroll
            for (int mt = 0; mt < 2; mt++)
#pragma unroll
                for (int nt = 0; nt < 8; nt++)
                    mma_tf32(acc[mt][nt], a[mt], b[nt >> 1][nt & 1], b[nt >> 1][2 + (nt & 1)]);
        }
        if (lane == 0) mbar_arrive(sbase + OFF_EMPTY + st * 8);
        if (++st == PIPE) { st = 0; ph ^= 1; }
    }

    // ---- epilogue: exp(logit) -> out, per-row sums -> g_rowsum ----
    const float invT = 1.4426950408889634f / tptr[0];   // log2(e)/T
    const int qrow = lane >> 2;
    const int qc = 2 * (lane & 3);
    float inb[8][2];
#pragma unroll
    for (int nt = 0; nt < 8; nt++) {
        int col = p0 + wn * 64 + nt * 8 + qc;
        inb[nt][0] = __ldg(g_inv_nb + col);
        inb[nt][1] = __ldg(g_inv_nb + col + 1);
    }
#pragma unroll
    for (int mt = 0; mt < 2; mt++) {
#pragma unroll
        for (int h = 0; h < 2; h++) {
            int row = n0 + wm * 32 + mt * 16 + h * 8 + qrow;
            float s = __ldg(g_inv_na + row) * invT;
            float rs = 0.0f;
            float* orow = out + (size_t)row * P + p0 + wn * 64 + qc;
#pragma unroll
            for (int nt = 0; nt < 8; nt++) {
                float e0 = ex2(acc[mt][nt][2 * h] * s * inb[nt][0]);
                float e1 = ex2(acc[mt][nt][2 * h + 1] * s * inb[nt][1]);
                rs += e0 + e1;
                *(float2*)(orow + nt * 8) = make_float2(e0, e1);
            }
            rs += __shfl_xor_sync(0xffffffffu, rs, 1);
            rs += __shfl_xor_sync(0xffffffffu, rs, 2);
            if ((lane & 3) == 0) atomicAdd(&g_rowsum[row], rs);
        }
    }
}

// ---------------------------------------------------------------------------
// Kernel 3: q = e / rowsum
// ---------------------------------------------------------------------------
__global__ void scale_kernel(float* __restrict__ out, int P) {
    int row = blockIdx.x;
    int c = (blockIdx.y * blockDim.x + threadIdx.x) * 4;
    float inv = 1.0f / g_rowsum[row];
    float4* p = (float4*)(out + (size_t)row * P + c);
    float4 v = *p;
    v.x *= inv; v.y *= inv; v.z *= inv; v.w *= inv;
    *p = v;
}

// ---------------------------------------------------------------------------
extern "C" void kernel_launch(void* const* d_in, const int* in_sizes, int n_in,
                              void* d_out, int out_size) {
    const float* emb = (const float*)d_in[0];
    const float* proto = (const float*)d_in[1];
    const float* temp = (const float*)d_in[2];
    float* out = (float*)d_out;
    const int N = in_sizes[0] / D_DIM;
    const int P = in_sizes[1] / D_DIM;

    typedef CUresult (*EncodeFn)(CUtensorMap*, CUtensorMapDataType, cuuint32_t, void*,
                                 const cuuint64_t*, const cuuint64_t*, const cuuint32_t*,
                                 const cuuint32_t*, CUtensorMapInterleave, CUtensorMapSwizzle,
                                 CUtensorMapL2promotion, CUtensorMapFloatOOBfill);
    EncodeFn encode = nullptr;
    cudaDriverEntryPointQueryResult qr;
    cudaGetDriverEntryPoint("cuTensorMapEncodeTiled", (void**)&encode,
                            cudaEnableDefault, &qr);

    CUtensorMap tma_a{}, tma_b{};
    {
        cuuint64_t dims[2] = {(cuuint64_t)D_DIM, (cuuint64_t)N};
        cuuint64_t strides[1] = {(cuuint64_t)D_DIM * 4};
        cuuint32_t box[2] = {KC, TM};
        cuuint32_t es[2] = {1, 1};
        encode(&tma_a, CU_TENSOR_MAP_DATA_TYPE_FLOAT32, 2, (void*)emb, dims, strides, box, es,
               CU_TENSOR_MAP_INTERLEAVE_NONE, CU_TENSOR_MAP_SWIZZLE_128B,
               CU_TENSOR_MAP_L2_PROMOTION_L2_128B, CU_TENSOR_MAP_FLOAT_OOB_FILL_NONE);
    }
    {
        cuuint64_t dims[2] = {(cuuint64_t)D_DIM, (cuuint64_t)P};
        cuuint64_t strides[1] = {(cuuint64_t)D_DIM * 4};
        cuuint32_t box[2] = {KC, TN};
        cuuint32_t es[2] = {1, 1};
        encode(&tma_b, CU_TENSOR_MAP_DATA_TYPE_FLOAT32, 2, (void*)proto, dims, strides, box, es,
               CU_TENSOR_MAP_INTERLEAVE_NONE, CU_TENSOR_MAP_SWIZZLE_128B,
               CU_TENSOR_MAP_L2_PROMOTION_L2_128B, CU_TENSOR_MAP_FLOAT_OOB_FILL_NONE);
    }

    // 1) norms + rowsum zeroing (warp per row)
    int rows = N + P;
    norm_kernel<<<(rows * 32 + 255) / 256, 256>>>(emb, proto, N, P);

    // 2) mma.sync tf32 GEMM + exp + rowsum (one block per 128x128 tile;
    //    p iterates fastest so co-scheduled blocks share A in L2)
    int NT = (N / TM) * (P / TN);
    cudaFuncSetAttribute(gemm_kernel, cudaFuncAttributeMaxDynamicSharedMemorySize, SMEM_TOTAL);
    gemm_kernel<<<NT, 288, SMEM_TOTAL>>>(tma_a, tma_b, temp, out, N, P);

    // 3) scale by 1/rowsum
    dim3 sgrid(N, P / 1024);
    scale_kernel<<<sgrid, 256>>>(out, P);
}

// round 4
// speedup vs baseline: 6.8470x; 1.6932x over previous
#include <cuda_runtime.h>
#include <cuda.h>
#include <cuda_fp16.h>
#include <cstdint>
#include <math.h>

// q[n][p] = softmax_p( <emb_n/|emb_n|, c_p/|c_p|> / T ), no max-subtraction
// (logits bounded in [-10,10], softmax shift-invariant).
// compute_103 toolchain (no 'a') -> tcgen05 unavailable; use full-rate fp16
// mma.sync.m16n8k16 with pre-normalized fp16 operands (fp16 mantissa == tf32
// mantissa, so accuracy matches the tf32 path measured at 2.9e-4).

#define D_DIM 768
#define TM 128
#define TN 128
#define KC 64                        // K halves per chunk (128B rows, SW128)
#define NCH (D_DIM / KC)             // 12
#define PIPE 3
#define A_ST (TM * KC * 2)           // 16384 B
#define B_ST (TN * KC * 2)           // 16384 B
#define SMEM_A_OFF 1024
#define SMEM_B_OFF (SMEM_A_OFF + PIPE * A_ST)
#define SMEM_TOTAL (SMEM_B_OFF + PIPE * B_ST)   // 99328 B -> 2 CTAs/SM

#define OFF_FULL  0
#define OFF_EMPTY 32

#define MAXN 65536
#define MAXP 4096
__device__ __half g_a16[(size_t)MAXN * D_DIM];   // normalized emb, fp16
__device__ __half g_b16[(size_t)MAXP * D_DIM];   // normalized prototypes, fp16
__device__ float g_rowsum[MAXN];

// ---------------------------------------------------------------------------
// PTX helpers
// ---------------------------------------------------------------------------
__device__ __forceinline__ uint32_t smem_u32(const void* p) {
    uint32_t a;
    asm("{ .reg .u64 t; cvta.to.shared.u64 t, %1; cvt.u32.u64 %0, t; }" : "=r"(a) : "l"(p));
    return a;
}
__device__ __forceinline__ void mbar_init(uint32_t bar, uint32_t cnt) {
    asm volatile("mbarrier.init.shared.b64 [%0], %1;" :: "r"(bar), "r"(cnt) : "memory");
}
__device__ __forceinline__ void mbar_expect_tx(uint32_t bar, uint32_t bytes) {
    asm volatile("mbarrier.arrive.expect_tx.shared.b64 _, [%0], %1;" :: "r"(bar), "r"(bytes) : "memory");
}
__device__ __forceinline__ void mbar_arrive(uint32_t bar) {
    asm volatile("mbarrier.arrive.shared.b64 _, [%0];" :: "r"(bar) : "memory");
}
__device__ __forceinline__ void mbar_wait(uint32_t bar, uint32_t parity) {
    uint32_t done;
    asm volatile(
        "{ .reg .pred p; mbarrier.try_wait.parity.acquire.cta.shared::cta.b64 p, [%1], %2;"
        " selp.b32 %0, 1, 0, p; }" : "=r"(done) : "r"(bar), "r"(parity) : "memory");
    if (!done) {
        asm volatile(
            "{ .reg .pred P1; WL%=:"
            " mbarrier.try_wait.parity.acquire.cta.shared::cta.b64 P1, [%0], %1, 0x989680;"
            " @P1 bra.uni WD%=; bra.uni WL%=; WD%=: }"
            :: "r"(bar), "r"(parity) : "memory");
    }
}
__device__ __forceinline__ void tma2d(uint32_t dst, const void* map, int x, int y, uint32_t bar) {
    asm volatile(
        "cp.async.bulk.tensor.2d.shared::cta.global.tile.mbarrier::complete_tx::bytes "
        "[%0], [%1, {%2, %3}], [%4];"
        :: "r"(dst), "l"(map), "r"(x), "r"(y), "r"(bar) : "memory");
}
__device__ __forceinline__ uint32_t swz(uint32_t off) {   // SW128 (128B rows)
    return off ^ ((off >> 3) & 0x70);
}
__device__ __forceinline__ void ldsm4(uint32_t* r, uint32_t addr) {
    asm volatile("ldmatrix.sync.aligned.m8n8.x4.shared.b16 {%0,%1,%2,%3}, [%4];"
                 : "=r"(r[0]), "=r"(r[1]), "=r"(r[2]), "=r"(r[3]) : "r"(addr));
}
__device__ __forceinline__ void mma_f16(float* d, const uint32_t* a, uint32_t b0, uint32_t b1) {
    asm volatile(
        "mma.sync.aligned.m16n8k16.row.col.f32.f16.f16.f32 "
        "{%0,%1,%2,%3}, {%4,%5,%6,%7}, {%8,%9}, {%0,%1,%2,%3};"
        : "+f"(d[0]), "+f"(d[1]), "+f"(d[2]), "+f"(d[3])
        : "r"(a[0]), "r"(a[1]), "r"(a[2]), "r"(a[3]), "r"(b0), "r"(b1));
}
__device__ __forceinline__ float ex2(float x) {
    float y;
    asm("ex2.approx.ftz.f32 %0, %1;" : "=f"(y) : "f"(x));
    return y;
}

// ---------------------------------------------------------------------------
// Kernel 1: warp-per-row: fp32 L2 norm, then write normalized fp16 row.
// Also zeroes g_rowsum.
// ---------------------------------------------------------------------------
__global__ void conv_kernel(const float* __restrict__ A, const float* __restrict__ B,
                            int N, int P) {
    int w = (blockIdx.x * blockDim.x + threadIdx.x) >> 5;
    int lane = threadIdx.x & 31;
    if (w >= N + P) return;
    const float4* src;
    __half2* dst;
    if (w < N) {
        src = (const float4*)(A + (size_t)w * D_DIM);
        dst = (__half2*)(g_a16 + (size_t)w * D_DIM);
        if (lane == 0) g_rowsum[w] = 0.0f;
    } else {
        int r = w - N;
        src = (const float4*)(B + (size_t)r * D_DIM);
        dst = (__half2*)(g_b16 + (size_t)r * D_DIM);
    }
    float4 v[D_DIM / 128];           // 6 groups of float4 per lane
    float ss = 0.0f;
#pragma unroll
    for (int i = 0; i < D_DIM / 128; i++) {
        v[i] = src[lane + 32 * i];
        ss += v[i].x * v[i].x + v[i].y * v[i].y + v[i].z * v[i].z + v[i].w * v[i].w;
    }
#pragma unroll
    for (int o = 16; o; o >>= 1) ss += __shfl_xor_sync(0xffffffffu, ss, o);
    float inv = 1.0f / fmaxf(sqrtf(ss), 1e-12f);
#pragma unroll
    for (int i = 0; i < D_DIM / 128; i++) {
        __half2 h0 = __floats2half2_rn(v[i].x * inv, v[i].y * inv);
        __half2 h1 = __floats2half2_rn(v[i].z * inv, v[i].w * inv);
        dst[(lane + 32 * i) * 2] = h0;
        dst[(lane + 32 * i) * 2 + 1] = h1;
    }
}

// ---------------------------------------------------------------------------
// Kernel 2: one CTA per 128x128 tile. TMA producer warp + 8 fp16 mma.sync
// consumer warps. Fused exp + rowsum epilogue (operands pre-normalized, so
// logit = acc / T directly). 2 CTAs/SM.
// ---------------------------------------------------------------------------
__global__ void __launch_bounds__(288, 2)
gemm_kernel(const __grid_constant__ CUtensorMap tmap_a,
            const __grid_constant__ CUtensorMap tmap_b,
            const float* __restrict__ tptr,
            float* __restrict__ out,
            int N, int P) {
    extern __shared__ char smem[];
    uint32_t sbase = smem_u32(smem);
    const int tid = threadIdx.x, wid = tid >> 5, lane = tid & 31;
    const int ntp = P / TN;
    const int n0 = (blockIdx.x / ntp) * TM;
    const int p0 = (blockIdx.x % ntp) * TN;

    if (tid == 0) {
        for (int s = 0; s < PIPE; s++) {
            mbar_init(sbase + OFF_FULL + s * 8, 1);
            mbar_init(sbase + OFF_EMPTY + s * 8, 8);
        }
    }
    __syncthreads();
    asm volatile("fence.proxy.async.shared::cta;" ::: "memory");

    if (wid == 8) {
        if (lane == 0) {
            int st = 0, ph = 1;
            for (int c = 0; c < NCH; c++) {
                mbar_wait(sbase + OFF_EMPTY + st * 8, ph);
                mbar_expect_tx(sbase + OFF_FULL + st * 8, A_ST + B_ST);
                tma2d(sbase + SMEM_A_OFF + st * A_ST, &tmap_a, c * KC, n0,
                      sbase + OFF_FULL + st * 8);
                tma2d(sbase + SMEM_B_OFF + st * B_ST, &tmap_b, c * KC, p0,
                      sbase + OFF_FULL + st * 8);
                if (++st == PIPE) { st = 0; ph ^= 1; }
            }
        }
        return;
    }

    // consumers: warp (wm, wn) owns 32x64 subtile
    const int wm = wid >> 1;
    const int wn = wid & 1;
    const int lrow = lane & 15;
    const int lgrp = (lane >> 4) * 16;     // 16-byte column group

    float acc[2][8][4];
#pragma unroll
    for (int mt = 0; mt < 2; mt++)
#pragma unroll
        for (int nt = 0; nt < 8; nt++)
#pragma unroll
            for (int q = 0; q < 4; q++) acc[mt][nt][q] = 0.0f;

    int st = 0, ph = 0;
    for (int c = 0; c < NCH; c++) {
        mbar_wait(sbase + OFF_FULL + st * 8, ph);
        const uint32_t abase = sbase + SMEM_A_OFF + st * A_ST;
        const uint32_t bbase = sbase + SMEM_B_OFF + st * B_ST;
#pragma unroll
        for (int ks = 0; ks < 4; ks++) {              // k16 per step
            const uint32_t kb = ks * 32 + lgrp;       // byte offset in 128B row
            uint32_t a[2][4];
#pragma unroll
            for (int mt = 0; mt < 2; mt++) {
                uint32_t off = (uint32_t)(wm * 32 + mt * 16 + lrow) * 128 + kb;
                ldsm4(a[mt], abase + swz(off));
            }
            uint32_t b[4][4];
#pragma unroll
            for (int bt = 0; bt < 4; bt++) {
                uint32_t off = (uint32_t)(wn * 64 + bt * 16 + lrow) * 128 + kb;
                ldsm4(b[bt], bbase + swz(off));
            }
#pragma unroll
            for (int mt = 0; mt < 2; mt++)
#pragma unroll
                for (int nt = 0; nt < 8; nt++)
                    mma_f16(acc[mt][nt], a[mt], b[nt >> 1][nt & 1], b[nt >> 1][2 + (nt & 1)]);
        }
        if (lane == 0) mbar_arrive(sbase + OFF_EMPTY + st * 8);
        if (++st == PIPE) { st = 0; ph ^= 1; }
    }

    // epilogue: e = exp2(acc * log2(e)/T); rowsum atomics
    const float s = 1.4426950408889634f / tptr[0];
    const int qrow = lane >> 2;
    const int qc = 2 * (lane & 3);
#pragma unroll
    for (int mt = 0; mt < 2; mt++) {
#pragma unroll
        for (int h = 0; h < 2; h++) {
            int row = n0 + wm * 32 + mt * 16 + h * 8 + qrow;
            float rs = 0.0f;
            float* orow = out + (size_t)row * P + p0 + wn * 64 + qc;
#pragma unroll
            for (int nt = 0; nt < 8; nt++) {
                float e0 = ex2(acc[mt][nt][2 * h] * s);
                float e1 = ex2(acc[mt][nt][2 * h + 1] * s);
                rs += e0 + e1;
                *(float2*)(orow + nt * 8) = make_float2(e0, e1);
            }
            rs += __shfl_xor_sync(0xffffffffu, rs, 1);
            rs += __shfl_xor_sync(0xffffffffu, rs, 2);
            if ((lane & 3) == 0) atomicAdd(&g_rowsum[row], rs);
        }
    }
}

// ---------------------------------------------------------------------------
// Kernel 3: q = e / rowsum
// ---------------------------------------------------------------------------
__global__ void scale_kernel(float* __restrict__ out, int P) {
    int row = blockIdx.x;
    int c = (blockIdx.y * blockDim.x + threadIdx.x) * 4;
    float inv = 1.0f / g_rowsum[row];
    float4* p = (float4*)(out + (size_t)row * P + c);
    float4 v = *p;
    v.x *= inv; v.y *= inv; v.z *= inv; v.w *= inv;
    *p = v;
}

// ---------------------------------------------------------------------------
extern "C" void kernel_launch(void* const* d_in, const int* in_sizes, int n_in,
                              void* d_out, int out_size) {
    const float* emb = (const float*)d_in[0];
    const float* proto = (const float*)d_in[1];
    const float* temp = (const float*)d_in[2];
    float* out = (float*)d_out;
    const int N = in_sizes[0] / D_DIM;
    const int P = in_sizes[1] / D_DIM;

    typedef CUresult (*EncodeFn)(CUtensorMap*, CUtensorMapDataType, cuuint32_t, void*,
                                 const cuuint64_t*, const cuuint64_t*, const cuuint32_t*,
                                 const cuuint32_t*, CUtensorMapInterleave, CUtensorMapSwizzle,
                                 CUtensorMapL2promotion, CUtensorMapFloatOOBfill);
    EncodeFn encode = nullptr;
    cudaDriverEntryPointQueryResult qr;
    cudaGetDriverEntryPoint("cuTensorMapEncodeTiled", (void**)&encode,
                            cudaEnableDefault, &qr);

    void *pa = nullptr, *pb = nullptr;
    cudaGetSymbolAddress(&pa, g_a16);
    cudaGetSymbolAddress(&pb, g_b16);

    CUtensorMap tma_a{}, tma_b{};
    {
        cuuint64_t dims[2] = {(cuuint64_t)D_DIM, (cuuint64_t)N};
        cuuint64_t strides[1] = {(cuuint64_t)D_DIM * 2};
        cuuint32_t box[2] = {KC, TM};
        cuuint32_t es[2] = {1, 1};
        encode(&tma_a, CU_TENSOR_MAP_DATA_TYPE_FLOAT16, 2, pa, dims, strides, box, es,
               CU_TENSOR_MAP_INTERLEAVE_NONE, CU_TENSOR_MAP_SWIZZLE_128B,
               CU_TENSOR_MAP_L2_PROMOTION_L2_128B, CU_TENSOR_MAP_FLOAT_OOB_FILL_NONE);
    }
    {
        cuuint64_t dims[2] = {(cuuint64_t)D_DIM, (cuuint64_t)P};
        cuuint64_t strides[1] = {(cuuint64_t)D_DIM * 2};
        cuuint32_t box[2] = {KC, TN};
        cuuint32_t es[2] = {1, 1};
        encode(&tma_b, CU_TENSOR_MAP_DATA_TYPE_FLOAT16, 2, pb, dims, strides, box, es,
               CU_TENSOR_MAP_INTERLEAVE_NONE, CU_TENSOR_MAP_SWIZZLE_128B,
               CU_TENSOR_MAP_L2_PROMOTION_L2_128B, CU_TENSOR_MAP_FLOAT_OOB_FILL_NONE);
    }

    // 1) normalize + fp16 convert (warp per row) + rowsum zeroing
    int rows = N + P;
    conv_kernel<<<(rows * 32 + 255) / 256, 256>>>(emb, proto, N, P);

    // 2) fp16 mma.sync GEMM + exp + rowsum (p fastest -> A-tile L2 sharing,
    //    B entirely L2-resident at 6.3 MB)
    int NT = (N / TM) * (P / TN);
    cudaFuncSetAttribute(gemm_kernel, cudaFuncAttributeMaxDynamicSharedMemorySize, SMEM_TOTAL);
    gemm_kernel<<<NT, 288, SMEM_TOTAL>>>(tma_a, tma_b, temp, out, N, P);

    // 3) scale by 1/rowsum
    dim3 sgrid(N, P / 1024);
    scale_kernel<<<sgrid, 256>>>(out, P);
}